// round 5
// baseline (speedup 1.0000x reference)
#include <cuda_runtime.h>
#include <math.h>

#define DIM 512
#define MARGIN 1.0f
#define RULE_WEIGHT 0.5f

#define MAX_B   1024
#define MAX_NEG 8192

// Scratch (allocation-free rule: __device__ globals)
__device__ float g_dpos[MAX_B];
__device__ float g_rule[MAX_B];
__device__ float g_dneg[MAX_NEG];
__device__ unsigned int g_ticket = 0;   // reset by last block each call

__device__ __forceinline__ float warp_red(float v) {
#pragma unroll
    for (int o = 16; o; o >>= 1) v += __shfl_xor_sync(0xffffffffu, v, o);
    return v;
}

// TransH distance from register-resident difference hd = he - te.
// c = hd.w / w.w ;  d = || hd + re - c*w ||
__device__ __forceinline__ float dist_from_hd(
    const float4 hd[4],
    const float* __restrict__ rel, const float* __restrict__ nv,
    int r, int lane)
{
    const float4* w4  = reinterpret_cast<const float4*>(nv  + (size_t)r * DIM);
    const float4* re4 = reinterpret_cast<const float4*>(rel + (size_t)r * DIM);
    float4 w[4], re[4];
    float ww = 0.f, dw = 0.f;
#pragma unroll
    for (int i = 0; i < 4; i++) {
        w[i]  = w4[lane + 32 * i];
        re[i] = re4[lane + 32 * i];
        ww += w[i].x * w[i].x + w[i].y * w[i].y + w[i].z * w[i].z + w[i].w * w[i].w;
        dw += hd[i].x * w[i].x + hd[i].y * w[i].y + hd[i].z * w[i].z + hd[i].w * w[i].w;
    }
    ww = warp_red(ww);
    dw = warp_red(dw);
    float c = dw / ww;
    float ss = 0.f;
#pragma unroll
    for (int i = 0; i < 4; i++) {
        float dx = hd[i].x + re[i].x - c * w[i].x;
        float dy = hd[i].y + re[i].y - c * w[i].y;
        float dz = hd[i].z + re[i].z - c * w[i].z;
        float dw2 = hd[i].w + re[i].w - c * w[i].w;
        ss += dx * dx + dy * dy + dz * dz + dw2 * dw2;
    }
    ss = warp_red(ss);
    return sqrtf(ss);
}

// Flat warp-per-task dist + last-block reduction.
// Release/acquire via ONE __threadfence per block (tid 0 only, post-barrier);
// last block reads partials with __ldcg (L2-only) so L1 staleness is moot.
__global__ void __launch_bounds__(256)
fused_all(const int* __restrict__ pos, const int* __restrict__ neg,
          const int* __restrict__ rr1, const int* __restrict__ rr2,
          const float* __restrict__ rconf,
          const float* __restrict__ ent, const float* __restrict__ rel,
          const float* __restrict__ nv,
          float* __restrict__ out,
          int B, int NEG, int NR)
{
    int tid  = threadIdx.x;
    int gw   = (blockIdx.x * blockDim.x + tid) >> 5;
    int lane = tid & 31;

    // ---- Phase 1: independent warp-per-distance ----
    if (gw < B + NEG) {
        int h, r, t;
        bool is_pos = (gw < B);
        if (is_pos) {
            h = pos[3 * gw]; r = pos[3 * gw + 1]; t = pos[3 * gw + 2];
        } else {
            int k = gw - B;
            h = neg[3 * k]; r = neg[3 * k + 1]; t = neg[3 * k + 2];
        }

        const float4* he4 = reinterpret_cast<const float4*>(ent + (size_t)h * DIM);
        const float4* te4 = reinterpret_cast<const float4*>(ent + (size_t)t * DIM);
        float4 hd[4];
#pragma unroll
        for (int i = 0; i < 4; i++) {
            float4 a = he4[lane + 32 * i];
            float4 b = te4[lane + 32 * i];
            hd[i].x = a.x - b.x; hd[i].y = a.y - b.y;
            hd[i].z = a.z - b.z; hd[i].w = a.w - b.w;
        }

        float d = dist_from_hd(hd, rel, nv, r, lane);

        if (is_pos) {
            // Only rules with rule_r1[j] == r contribute (mask exact-zeros the rest).
            float racc = 0.f;
            for (int j = 0; j < NR; j++) {
                if (rr1[j] == r)
                    racc += rconf[j] * dist_from_hd(hd, rel, nv, rr2[j], lane);
            }
            if (lane == 0) { g_dpos[gw] = d; g_rule[gw] = racc; }
        } else {
            if (lane == 0) g_dneg[gw - B] = d;
        }
    }

    // ---- Phase 2: ticket; ONLY tid 0 fences (release, cumulative over barrier) ----
    __syncthreads();
    __shared__ unsigned int s_last;
    if (tid == 0) {
        __threadfence();                              // release this block's stores
        unsigned int t = atomicAdd(&g_ticket, 1u);
        s_last = (t == gridDim.x - 1) ? 1u : 0u;
        if (s_last) __threadfence();                  // acquire others' stores
    }
    __syncthreads();
    if (!s_last) return;

    // ---- Phase 3: last block reduces (L2-hot, __ldcg bypasses L1) ----
    __shared__ float s_dpos[MAX_B];
    __shared__ float sb[256];
    __shared__ float sr[256];
    int ratio = NEG / B;

    float racc = 0.f;
    for (int i = tid; i < B; i += 256) {
        s_dpos[i] = __ldcg(&g_dpos[i]);
        racc += __ldcg(&g_rule[i]);
    }
    __syncthreads();

    float acc = 0.f;
    const float4* n4 = reinterpret_cast<const float4*>(g_dneg);
    int nv4 = NEG >> 2;
    for (int q = tid; q < nv4; q += 256) {
        float4 v = __ldcg(&n4[q]);
        int kb = 4 * q;
        float v0 = MARGIN + s_dpos[kb / ratio]       - v.x; acc += (v0 > 0.f) ? v0 : 0.f;
        float v1 = MARGIN + s_dpos[(kb + 1) / ratio] - v.y; acc += (v1 > 0.f) ? v1 : 0.f;
        float v2 = MARGIN + s_dpos[(kb + 2) / ratio] - v.z; acc += (v2 > 0.f) ? v2 : 0.f;
        float v3 = MARGIN + s_dpos[(kb + 3) / ratio] - v.w; acc += (v3 > 0.f) ? v3 : 0.f;
    }
    for (int k = (nv4 << 2) + tid; k < NEG; k += 256) {
        float v = MARGIN + s_dpos[k / ratio] - __ldcg(&g_dneg[k]);
        acc += (v > 0.f) ? v : 0.f;
    }

    sb[tid] = acc; sr[tid] = racc;
    __syncthreads();
    for (int s = 128; s; s >>= 1) {
        if (tid < s) { sb[tid] += sb[tid + s]; sr[tid] += sr[tid + s]; }
        __syncthreads();
    }
    if (tid == 0) {
        out[0] = sb[0] / (float)NEG + RULE_WEIGHT * sr[0];
        g_ticket = 0;        // reset for next graph replay (deterministic)
    }
}

extern "C" void kernel_launch(void* const* d_in, const int* in_sizes, int n_in,
                              void* d_out, int out_size)
{
    const int*   pos   = (const int*)d_in[0];
    const int*   neg   = (const int*)d_in[1];
    const int*   rr1   = (const int*)d_in[2];
    const int*   rr2   = (const int*)d_in[3];
    const float* rconf = (const float*)d_in[4];
    const float* ent   = (const float*)d_in[5];
    const float* rel   = (const float*)d_in[6];
    const float* nv    = (const float*)d_in[7];

    int B   = in_sizes[0] / 3;
    int NEG = in_sizes[1] / 3;
    int NR  = in_sizes[2];

    int totalWarps = B + NEG;
    int blocks = (totalWarps * 32 + 255) / 256;

    fused_all<<<blocks, 256>>>(pos, neg, rr1, rr2, rconf, ent, rel, nv,
                               (float*)d_out, B, NEG, NR);
}

// round 6
// speedup vs baseline: 1.0252x; 1.0252x over previous
#include <cuda_runtime.h>
#include <math.h>

#define DIM 512
#define MARGIN 1.0f
#define RULE_WEIGHT 0.5f

#define MAX_B   1024
#define MAX_NEG 8192

// Scratch (allocation-free rule: __device__ globals)
__device__ float g_dpos[MAX_B];
__device__ float g_rule[MAX_B];
__device__ float g_dneg[MAX_NEG];

__device__ __forceinline__ float warp_red(float v) {
#pragma unroll
    for (int o = 16; o; o >>= 1) v += __shfl_xor_sync(0xffffffffu, v, o);
    return v;
}

// TransH distance from register-resident difference hd = he - te.
// c = hd.w / w.w ;  d = || hd + re - c*w ||
// re is NOT kept in registers: reloaded in the residual pass (L1/L2-hot),
// trading 16 registers for occupancy.
__device__ __forceinline__ float dist_from_hd(
    const float4 hd[4],
    const float* __restrict__ rel, const float* __restrict__ nv,
    int r, int lane)
{
    const float4* w4  = reinterpret_cast<const float4*>(nv  + (size_t)r * DIM);
    const float4* re4 = reinterpret_cast<const float4*>(rel + (size_t)r * DIM);
    float4 w[4];
    float ww = 0.f, dw = 0.f;
#pragma unroll
    for (int i = 0; i < 4; i++) {
        w[i] = w4[lane + 32 * i];
        ww += w[i].x * w[i].x + w[i].y * w[i].y + w[i].z * w[i].z + w[i].w * w[i].w;
        dw += hd[i].x * w[i].x + hd[i].y * w[i].y + hd[i].z * w[i].z + hd[i].w * w[i].w;
    }
    ww = warp_red(ww);
    dw = warp_red(dw);
    float c = dw / ww;
    float ss = 0.f;
#pragma unroll
    for (int i = 0; i < 4; i++) {
        float4 re = re4[lane + 32 * i];
        float dx = hd[i].x + re.x - c * w[i].x;
        float dy = hd[i].y + re.y - c * w[i].y;
        float dz = hd[i].z + re.z - c * w[i].z;
        float dq = hd[i].w + re.w - c * w[i].w;
        ss += dx * dx + dy * dy + dz * dz + dq * dq;
    }
    ss = warp_red(ss);
    return sqrtf(ss);
}

// Flat warp-per-task: [0,B) = pos triples (+rule terms), [B,B+NEG) = negs.
// __launch_bounds__(256, 4) caps regs at 64 -> 4 blocks/SM (occupancy lever).
__global__ void __launch_bounds__(256, 4)
dist_kernel(const int* __restrict__ pos, const int* __restrict__ neg,
            const int* __restrict__ rr1, const int* __restrict__ rr2,
            const float* __restrict__ rconf,
            const float* __restrict__ ent, const float* __restrict__ rel,
            const float* __restrict__ nv,
            int B, int NEG, int NR)
{
    int gw   = (blockIdx.x * blockDim.x + threadIdx.x) >> 5;
    int lane = threadIdx.x & 31;
    if (gw >= B + NEG) return;

    int h, r, t;
    bool is_pos = (gw < B);
    if (is_pos) {
        h = pos[3 * gw]; r = pos[3 * gw + 1]; t = pos[3 * gw + 2];
    } else {
        int k = gw - B;
        h = neg[3 * k]; r = neg[3 * k + 1]; t = neg[3 * k + 2];
    }

    const float4* he4 = reinterpret_cast<const float4*>(ent + (size_t)h * DIM);
    const float4* te4 = reinterpret_cast<const float4*>(ent + (size_t)t * DIM);
    float4 hd[4];
#pragma unroll
    for (int i = 0; i < 4; i++) {
        float4 a = he4[lane + 32 * i];
        float4 b = te4[lane + 32 * i];
        hd[i].x = a.x - b.x; hd[i].y = a.y - b.y;
        hd[i].z = a.z - b.z; hd[i].w = a.w - b.w;
    }

    float d = dist_from_hd(hd, rel, nv, r, lane);

    if (is_pos) {
        // Only rules with rule_r1[j] == r contribute (mask exact-zeros the rest).
        float racc = 0.f;
        for (int j = 0; j < NR; j++) {
            if (rr1[j] == r)
                racc += rconf[j] * dist_from_hd(hd, rel, nv, rr2[j], lane);
        }
        if (lane == 0) { g_dpos[gw] = d; g_rule[gw] = racc; }
    } else {
        if (lane == 0) g_dneg[gw - B] = d;
    }
}

// Reduce: launched with Programmatic Dependent Launch so its launch latency
// overlaps dist_kernel execution; cudaGridDependencySynchronize() provides
// the ordering + visibility (implicit trigger at primary completion).
__global__ void __launch_bounds__(256)
final_reduce(float* __restrict__ out, int B, int NEG)
{
    cudaGridDependencySynchronize();

    __shared__ float s_dpos[MAX_B];
    __shared__ float sb[256];
    __shared__ float sr[256];
    int tid = threadIdx.x;
    int ratio = NEG / B;

    float racc = 0.f;
    for (int i = tid; i < B; i += 256) {
        s_dpos[i] = g_dpos[i];
        racc += g_rule[i];
    }
    __syncthreads();

    float acc = 0.f;
    const float4* n4 = reinterpret_cast<const float4*>(g_dneg);
    int nv4 = NEG >> 2;
    for (int q = tid; q < nv4; q += 256) {
        float4 v = n4[q];
        int kb = 4 * q;
        float v0 = MARGIN + s_dpos[kb / ratio]       - v.x; acc += (v0 > 0.f) ? v0 : 0.f;
        float v1 = MARGIN + s_dpos[(kb + 1) / ratio] - v.y; acc += (v1 > 0.f) ? v1 : 0.f;
        float v2 = MARGIN + s_dpos[(kb + 2) / ratio] - v.z; acc += (v2 > 0.f) ? v2 : 0.f;
        float v3 = MARGIN + s_dpos[(kb + 3) / ratio] - v.w; acc += (v3 > 0.f) ? v3 : 0.f;
    }
    for (int k = (nv4 << 2) + tid; k < NEG; k += 256) {
        float v = MARGIN + s_dpos[k / ratio] - g_dneg[k];
        acc += (v > 0.f) ? v : 0.f;
    }

    sb[tid] = acc; sr[tid] = racc;
    __syncthreads();
    for (int s = 128; s; s >>= 1) {
        if (tid < s) { sb[tid] += sb[tid + s]; sr[tid] += sr[tid + s]; }
        __syncthreads();
    }
    if (tid == 0)
        out[0] = sb[0] / (float)NEG + RULE_WEIGHT * sr[0];
}

extern "C" void kernel_launch(void* const* d_in, const int* in_sizes, int n_in,
                              void* d_out, int out_size)
{
    const int*   pos   = (const int*)d_in[0];
    const int*   neg   = (const int*)d_in[1];
    const int*   rr1   = (const int*)d_in[2];
    const int*   rr2   = (const int*)d_in[3];
    const float* rconf = (const float*)d_in[4];
    const float* ent   = (const float*)d_in[5];
    const float* rel   = (const float*)d_in[6];
    const float* nv    = (const float*)d_in[7];

    int B   = in_sizes[0] / 3;
    int NEG = in_sizes[1] / 3;
    int NR  = in_sizes[2];

    int totalWarps = B + NEG;
    int blocks = (totalWarps * 32 + 255) / 256;

    dist_kernel<<<blocks, 256>>>(pos, neg, rr1, rr2, rconf, ent, rel, nv, B, NEG, NR);

    // PDL launch of the reduce: overlap its launch with dist_kernel.
    cudaLaunchConfig_t cfg = {};
    cfg.gridDim  = dim3(1, 1, 1);
    cfg.blockDim = dim3(256, 1, 1);
    cfg.dynamicSmemBytes = 0;
    cfg.stream = 0;   // same (legacy default) stream as the <<<>>> launch
    cudaLaunchAttribute attr[1];
    attr[0].id = cudaLaunchAttributeProgrammaticStreamSerialization;
    attr[0].val.programmaticStreamSerializationAllowed = 1;
    cfg.attrs = attr;
    cfg.numAttrs = 1;
    cudaLaunchKernelEx(&cfg, final_reduce, (float*)d_out, B, NEG);
}

// round 7
// speedup vs baseline: 1.1210x; 1.0934x over previous
#include <cuda_runtime.h>
#include <math.h>

#define DIM 512
#define MARGIN 1.0f
#define RULE_WEIGHT 0.5f

#define MAX_B   1024
#define MAX_NEG 8192

// Scratch (allocation-free rule: __device__ globals)
__device__ float g_dpos[MAX_B];
__device__ float g_rule[MAX_B];
__device__ float g_dneg[MAX_NEG];

__device__ __forceinline__ float warp_red(float v) {
#pragma unroll
    for (int o = 16; o; o >>= 1) v += __shfl_xor_sync(0xffffffffu, v, o);
    return v;
}

// TransH distance from register-resident difference hd = he - te.
// c = hd.w / w.w ;  d = || hd + re - c*w ||
// (R4 version: w AND re both register-resident — measured fastest.)
__device__ __forceinline__ float dist_from_hd(
    const float4 hd[4],
    const float* __restrict__ rel, const float* __restrict__ nv,
    int r, int lane)
{
    const float4* w4  = reinterpret_cast<const float4*>(nv  + (size_t)r * DIM);
    const float4* re4 = reinterpret_cast<const float4*>(rel + (size_t)r * DIM);
    float4 w[4], re[4];
    float ww = 0.f, dw = 0.f;
#pragma unroll
    for (int i = 0; i < 4; i++) {
        w[i]  = w4[lane + 32 * i];
        re[i] = re4[lane + 32 * i];
        ww += w[i].x * w[i].x + w[i].y * w[i].y + w[i].z * w[i].z + w[i].w * w[i].w;
        dw += hd[i].x * w[i].x + hd[i].y * w[i].y + hd[i].z * w[i].z + hd[i].w * w[i].w;
    }
    ww = warp_red(ww);
    dw = warp_red(dw);
    float c = dw / ww;
    float ss = 0.f;
#pragma unroll
    for (int i = 0; i < 4; i++) {
        float dx = hd[i].x + re[i].x - c * w[i].x;
        float dy = hd[i].y + re[i].y - c * w[i].y;
        float dz = hd[i].z + re[i].z - c * w[i].z;
        float dw2 = hd[i].w + re[i].w - c * w[i].w;
        ss += dx * dx + dy * dy + dz * dz + dw2 * dw2;
    }
    ss = warp_red(ss);
    return sqrtf(ss);
}

// Flat warp-per-task: [0,B) = pos triples (+rule terms), [B,B+NEG) = negs.
// EXACT R4 structure (no launch_bounds min-blocks cap — it caused spills).
__global__ void __launch_bounds__(256)
dist_kernel(const int* __restrict__ pos, const int* __restrict__ neg,
            const int* __restrict__ rr1, const int* __restrict__ rr2,
            const float* __restrict__ rconf,
            const float* __restrict__ ent, const float* __restrict__ rel,
            const float* __restrict__ nv,
            int B, int NEG, int NR)
{
    int gw   = (blockIdx.x * blockDim.x + threadIdx.x) >> 5;
    int lane = threadIdx.x & 31;
    if (gw >= B + NEG) return;

    int h, r, t;
    bool is_pos = (gw < B);
    if (is_pos) {
        h = pos[3 * gw]; r = pos[3 * gw + 1]; t = pos[3 * gw + 2];
    } else {
        int k = gw - B;
        h = neg[3 * k]; r = neg[3 * k + 1]; t = neg[3 * k + 2];
    }

    const float4* he4 = reinterpret_cast<const float4*>(ent + (size_t)h * DIM);
    const float4* te4 = reinterpret_cast<const float4*>(ent + (size_t)t * DIM);
    float4 hd[4];
#pragma unroll
    for (int i = 0; i < 4; i++) {
        float4 a = he4[lane + 32 * i];
        float4 b = te4[lane + 32 * i];
        hd[i].x = a.x - b.x; hd[i].y = a.y - b.y;
        hd[i].z = a.z - b.z; hd[i].w = a.w - b.w;
    }

    float d = dist_from_hd(hd, rel, nv, r, lane);

    if (is_pos) {
        // Only rules with rule_r1[j] == r contribute (mask exact-zeros the rest).
        float racc = 0.f;
        for (int j = 0; j < NR; j++) {
            if (rr1[j] == r)
                racc += rconf[j] * dist_from_hd(hd, rel, nv, rr2[j], lane);
        }
        if (lane == 0) { g_dpos[gw] = d; g_rule[gw] = racc; }
    } else {
        if (lane == 0) g_dneg[gw - B] = d;
    }
}

// Reduce (R4's 1024-thread version) launched via PDL: its launch/prologue
// overlaps dist_kernel; cudaGridDependencySynchronize() provides ordering +
// memory visibility (implicit trigger at primary completion).
__global__ void __launch_bounds__(1024)
final_reduce(float* __restrict__ out, int B, int NEG)
{
    cudaGridDependencySynchronize();

    __shared__ float s_dpos[MAX_B];
    __shared__ float s_part[32];
    __shared__ float s_partr[32];
    int tid = threadIdx.x;
    int ratio = NEG / B;

    float racc = 0.f;
    for (int i = tid; i < B; i += 1024) {
        s_dpos[i] = g_dpos[i];
        racc += g_rule[i];
    }
    __syncthreads();

    float acc = 0.f;
    const float4* n4 = reinterpret_cast<const float4*>(g_dneg);
    int nv4 = NEG >> 2;
    for (int q = tid; q < nv4; q += 1024) {
        float4 v = n4[q];
        int kb = 4 * q;
        float v0 = MARGIN + s_dpos[kb / ratio]       - v.x; acc += (v0 > 0.f) ? v0 : 0.f;
        float v1 = MARGIN + s_dpos[(kb + 1) / ratio] - v.y; acc += (v1 > 0.f) ? v1 : 0.f;
        float v2 = MARGIN + s_dpos[(kb + 2) / ratio] - v.z; acc += (v2 > 0.f) ? v2 : 0.f;
        float v3 = MARGIN + s_dpos[(kb + 3) / ratio] - v.w; acc += (v3 > 0.f) ? v3 : 0.f;
    }
    for (int k = (nv4 << 2) + tid; k < NEG; k += 1024) {
        float v = MARGIN + s_dpos[k / ratio] - g_dneg[k];
        acc += (v > 0.f) ? v : 0.f;
    }

    acc  = warp_red(acc);
    racc = warp_red(racc);
    int wid = tid >> 5, lane = tid & 31;
    if (lane == 0) { s_part[wid] = acc; s_partr[wid] = racc; }
    __syncthreads();
    if (wid == 0) {
        float a  = s_part[lane];
        float rr = s_partr[lane];
        a  = warp_red(a);
        rr = warp_red(rr);
        if (lane == 0)
            out[0] = a / (float)NEG + RULE_WEIGHT * rr;
    }
}

extern "C" void kernel_launch(void* const* d_in, const int* in_sizes, int n_in,
                              void* d_out, int out_size)
{
    const int*   pos   = (const int*)d_in[0];
    const int*   neg   = (const int*)d_in[1];
    const int*   rr1   = (const int*)d_in[2];
    const int*   rr2   = (const int*)d_in[3];
    const float* rconf = (const float*)d_in[4];
    const float* ent   = (const float*)d_in[5];
    const float* rel   = (const float*)d_in[6];
    const float* nv    = (const float*)d_in[7];

    int B   = in_sizes[0] / 3;
    int NEG = in_sizes[1] / 3;
    int NR  = in_sizes[2];

    int totalWarps = B + NEG;
    int blocks = (totalWarps * 32 + 255) / 256;

    dist_kernel<<<blocks, 256>>>(pos, neg, rr1, rr2, rconf, ent, rel, nv, B, NEG, NR);

    // PDL launch of the reduce: overlap its launch latency with dist_kernel.
    cudaLaunchConfig_t cfg = {};
    cfg.gridDim  = dim3(1, 1, 1);
    cfg.blockDim = dim3(1024, 1, 1);
    cfg.dynamicSmemBytes = 0;
    cfg.stream = 0;
    cudaLaunchAttribute attr[1];
    attr[0].id = cudaLaunchAttributeProgrammaticStreamSerialization;
    attr[0].val.programmaticStreamSerializationAllowed = 1;
    cfg.attrs = attr;
    cfg.numAttrs = 1;
    cudaLaunchKernelEx(&cfg, final_reduce, (float*)d_out, B, NEG);
}